// round 14
// baseline (speedup 1.0000x reference)
#include <cuda_runtime.h>
#include <cuda_bf16.h>
#include <stdint.h>

#define NODES_MAX 50000
#define HID 128
#define ZD 64
#define NPB 16          // nodes per block in K0
#define TM 128          // edges per tile in K2
#define K1_BLOCKS 1184  // 148 SMs * 8
#define K2_GRID 148

typedef unsigned long long u64;
typedef unsigned int u32;

// ---------------- static device scratch ----------------
__device__ float  g_A[NODES_MAX * HID];     // z @ W1[0:64]   (fp32, for K2 producer)
__device__ float  g_B[NODES_MAX * HID];     // z @ W1[64:128]
__device__ unsigned short g_Abf[NODES_MAX * HID];  // bf16 copies (for K1 stats: half traffic)
__device__ unsigned short g_Bbf[NODES_MAX * HID];
__device__ float  g_d[HID];                 // c @ W1[128:132] + b1
__device__ double g_sum[HID];
__device__ double g_sumsq[HID];
__device__ unsigned short g_Whi[16384];     // BN-folded W2 bf16-hi, MMA swizzled layout
__device__ unsigned short g_Wlo[16384];     // bf16-lo residual
__device__ float2 g_w3b2[HID];              // (b2_folded, w3) per feature
__device__ int    g_is64;

// ---------------- helpers ----------------
__device__ __forceinline__ u32 smem_u32(const void* p) {
    u32 a;
    asm("{ .reg .u64 t; cvta.to.shared.u64 t, %1; cvt.u32.u64 %0, t; }" : "=r"(a) : "l"(p));
    return a;
}
// packed bf16x2 convert: low half <- lo, high half <- hi
__device__ __forceinline__ u32 bf2(float lo, float hi) {
    u32 r;
    asm("cvt.rn.bf16x2.f32 %0, %1, %2;" : "=r"(r) : "f"(hi), "f"(lo));
    return r;
}
__device__ __forceinline__ void ldsm4(u32* r, u32 addr) {
    asm volatile("ldmatrix.sync.aligned.m8n8.x4.shared.b16 {%0,%1,%2,%3}, [%4];"
                 : "=r"(r[0]), "=r"(r[1]), "=r"(r[2]), "=r"(r[3]) : "r"(addr));
}
__device__ __forceinline__ void mma16816(float* c, const u32* a, u32 b0, u32 b1) {
    asm volatile(
        "mma.sync.aligned.m16n8k16.row.col.f32.bf16.bf16.f32 "
        "{%0,%1,%2,%3}, {%4,%5,%6,%7}, {%8,%9}, {%0,%1,%2,%3};"
        : "+f"(c[0]), "+f"(c[1]), "+f"(c[2]), "+f"(c[3])
        : "r"(a[0]), "r"(a[1]), "r"(a[2]), "r"(a[3]), "r"(b0), "r"(b1));
}

// MMA-layout byte offset for element (row r, col k) in a 128x128 bf16 K-major
// SW128 blocked-atom tile: atom = 8 rows x 64 bf16 (1024B), 16 atom-rows x 2 atom-cols.
__device__ __forceinline__ int bofs(int r, int k) {
    int off = ((r >> 3) << 10) + ((k >> 6) << 14) + ((r & 7) << 7) + ((k & 63) << 1);
    return off ^ ((off >> 3) & 0x70);
}

// ---------------- K0: per-node partial products (+fused detect & k0b in extra block) ----------------
__global__ void k0_nodes(const float* __restrict__ z, const float* __restrict__ W1, int N,
                         const unsigned int* __restrict__ eiw,
                         const float* __restrict__ c, const float* __restrict__ b1) {
    __shared__ float zs[NPB * ZD];
    int tid = threadIdx.x;

    if (blockIdx.x == gridDim.x - 1) {
        // --- fused k_detect: is edge_index int64 or int32? ---
        __shared__ int nz;
        if (tid == 0) nz = 0;
        __syncthreads();
        if (eiw[2 * tid + 1] != 0u) atomicAdd(&nz, 1);
        __syncthreads();
        if (tid == 0) g_is64 = (nz == 0) ? 1 : 0;
        // --- fused k0b: d = c@W1c + b1, zero BN accumulators ---
        float v = b1[tid];
#pragma unroll
        for (int k = 0; k < 4; k++) v = fmaf(c[k], W1[(2 * ZD + k) * HID + tid], v);
        g_d[tid]     = v;
        g_sum[tid]   = 0.0;
        g_sumsq[tid] = 0.0;
        return;
    }

    int base = blockIdx.x * NPB;
    int nn   = N - base; if (nn > NPB) nn = NPB;

    for (int i = tid; i < nn * ZD; i += 128) zs[i] = z[base * ZD + i];
    __syncthreads();

    float a[NPB], b[NPB];
#pragma unroll
    for (int n = 0; n < NPB; n++) { a[n] = 0.f; b[n] = 0.f; }

#pragma unroll 8
    for (int k = 0; k < ZD; k++) {
        float ws = W1[k * HID + tid];
        float wd = W1[(ZD + k) * HID + tid];
#pragma unroll
        for (int n = 0; n < NPB; n++) {
            float zk = zs[n * ZD + k];
            a[n] = fmaf(zk, ws, a[n]);
            b[n] = fmaf(zk, wd, b[n]);
        }
    }
    for (int n = 0; n < nn; n++) {
        int idx = (base + n) * HID + tid;
        g_A[idx] = a[n];
        g_B[idx] = b[n];
        __nv_bfloat16 ab = __float2bfloat16(a[n]);
        __nv_bfloat16 bb = __float2bfloat16(b[n]);
        g_Abf[idx] = *(const unsigned short*)&ab;
        g_Bbf[idx] = *(const unsigned short*)&bb;
    }
}

// ---------------- K1: BN statistics pass (bf16 gathers -> half L2 traffic) ----------------
template<bool IS64>
__device__ __forceinline__ int ldi(const void* ei, long long pos) {
    return IS64 ? (int)((const long long*)ei)[pos] : ((const int*)ei)[pos];
}

template<bool IS64>
__device__ __forceinline__ void k1_body(const void* __restrict__ ei, int E) {
    int j = threadIdx.x;
    float dreg = g_d[j];
    const __nv_bfloat16* Ab = (const __nv_bfloat16*)g_Abf;
    const __nv_bfloat16* Bb = (const __nv_bfloat16*)g_Bbf;

    int per = (E + gridDim.x - 1) / (int)gridDim.x;
    int e0 = blockIdx.x * per;
    int e1 = e0 + per; if (e1 > E) e1 = E;

    float s1 = 0.f, s2 = 0.f;
    int e = e0;
    for (; e + 16 <= e1; e += 16) {
        int s[16], t[16];
#pragma unroll
        for (int i = 0; i < 16; i++) s[i] = ldi<IS64>(ei, e + i);
#pragma unroll
        for (int i = 0; i < 16; i++) t[i] = ldi<IS64>(ei, (long long)E + e + i);
        __nv_bfloat16 av[16], bv[16];
#pragma unroll
        for (int i = 0; i < 16; i++) { av[i] = Ab[s[i] * HID + j]; bv[i] = Bb[t[i] * HID + j]; }
#pragma unroll
        for (int i = 0; i < 16; i++) {
            float h = fmaxf(__bfloat162float(av[i]) + __bfloat162float(bv[i]) + dreg, 0.f);
            s1 += h; s2 = fmaf(h, h, s2);
        }
    }
    for (; e < e1; e++) {
        int s = ldi<IS64>(ei, e);
        int t = ldi<IS64>(ei, (long long)E + e);
        float h = fmaxf(__bfloat162float(Ab[s * HID + j]) + __bfloat162float(Bb[t * HID + j]) + dreg, 0.f);
        s1 += h; s2 = fmaf(h, h, s2);
    }
    atomicAdd(&g_sum[j],   (double)s1);
    atomicAdd(&g_sumsq[j], (double)s2);
}

__global__ void __launch_bounds__(128, 8) k1_stats(const void* __restrict__ ei, int E) {
    if (g_is64) k1_body<true>(ei, E);
    else        k1_body<false>(ei, E);
}

// ---------------- K1.5: fold BN into W2 (PARALLEL: 128 blocks, one per output feature) ----------------
__global__ void k15_fold(const float* __restrict__ gamma, const float* __restrict__ beta,
                         const float* __restrict__ W2, const float* __restrict__ b2,
                         const float* __restrict__ W3, double invE) {
    __shared__ float red[4];
    int i = blockIdx.x;    // output feature f
    int k = threadIdx.x;   // input feature k
    int lane = k & 31, wrp = k >> 5;

    double m = g_sum[k] * invE;
    double v = g_sumsq[k] * invE - m * m;
    float x = (float)v + 1e-5f;
    float s = rsqrtf(x);
    s = s * (1.5f - 0.5f * x * s * s);  // Newton refine
    float g = s * gamma[k];
    float gsc_k = g;
    float gsh_k = beta[k] - (float)m * g;

    float w = W2[k * HID + i];           // W2[k][f=i]
    float wf = gsc_k * w;                // BN scale folded
    __nv_bfloat16 hb = __float2bfloat16(wf);
    float hf = __bfloat162float(hb);
    __nv_bfloat16 lb = __float2bfloat16(wf - hf);
    int o = bofs(i, k) >> 1;             // row = feature f, col = k
    g_Whi[o] = *(const unsigned short*)&hb;
    g_Wlo[o] = *(const unsigned short*)&lb;

    float bb = gsh_k * w;
#pragma unroll
    for (int d = 16; d > 0; d >>= 1) bb += __shfl_xor_sync(0xffffffffu, bb, d);
    if (lane == 0) red[wrp] = bb;
    __syncthreads();
    if (k == 0) {
        float tot = red[0] + red[1] + red[2] + red[3];
        g_w3b2[i] = make_float2(b2[i] + tot, W3[i]);
    }
}

// ---------------- K2: warp-specialized producer/consumer ----------------
// 384 threads: warps 0-7 = MMA consumers (each m=64 x n=32),
// warps 8-11 = pipelined gather producers + output epilogue.
// smem (1024-aligned base):
#define OFF_WHI 0
#define OFF_WLO 32768
#define OFF_H(buf, part) (65536 + (buf) * 65536 + (part) * 32768)
#define OFF_SWB 196608          // w3b2 float2[128] (1KB)
#define OFF_SRED 197632         // sred[4][128] floats
#define K2_SMEM (199680 + 1024)

// producer: coalesced gather + relu + bf16 hi/lo split, SOFTWARE-PIPELINED.
static __device__ __forceinline__ void k2_produce(
    int tile, long long E, int is64, const long long* p64, const int* p32,
    const float4* dq, char* aHi, char* aLo, int lg, int gr)
{
    int sa[8], ta[8];
#pragma unroll
    for (int p = 0; p < 8; p++) {
        long long ge = (long long)tile * TM + p * 16 + gr;
        long long g2 = (ge < E) ? ge : (long long)0;
        sa[p] = is64 ? (int)p64[g2] : p32[g2];
        ta[p] = is64 ? (int)p64[E + g2] : p32[E + g2];
    }

    float4 av[2][4], bv[2][4];
    {
        const float4* ap = (const float4*)(g_A + (size_t)sa[0] * HID) + lg;
        const float4* bp = (const float4*)(g_B + (size_t)ta[0] * HID) + lg;
#pragma unroll
        for (int i = 0; i < 4; i++) av[0][i] = ap[i * 8];
#pragma unroll
        for (int i = 0; i < 4; i++) bv[0][i] = bp[i * 8];
    }

#pragma unroll
    for (int p = 0; p < 8; p++) {
        int cur = p & 1;
        if (p < 7) {
            const float4* ap = (const float4*)(g_A + (size_t)sa[p + 1] * HID) + lg;
            const float4* bp = (const float4*)(g_B + (size_t)ta[p + 1] * HID) + lg;
#pragma unroll
            for (int i = 0; i < 4; i++) av[cur ^ 1][i] = ap[i * 8];
#pragma unroll
            for (int i = 0; i < 4; i++) bv[cur ^ 1][i] = bp[i * 8];
        }
        int r = p * 16 + gr;
#pragma unroll
        for (int i = 0; i < 4; i++) {
            float4 d = dq[i];
            float4 a = av[cur][i], b = bv[cur][i];
            float h0 = fmaxf(a.x + b.x + d.x, 0.f);
            float h1 = fmaxf(a.y + b.y + d.y, 0.f);
            float h2 = fmaxf(a.z + b.z + d.z, 0.f);
            float h3 = fmaxf(a.w + b.w + d.w, 0.f);
            u32 ph0 = bf2(h0, h1), ph1 = bf2(h2, h3);
            float r00 = __uint_as_float(ph0 << 16);
            float r01 = __uint_as_float(ph0 & 0xFFFF0000u);
            float r10 = __uint_as_float(ph1 << 16);
            float r11 = __uint_as_float(ph1 & 0xFFFF0000u);
            u32 pl0 = bf2(h0 - r00, h1 - r01);
            u32 pl1 = bf2(h2 - r10, h3 - r11);
            int o = bofs(r, i * 32 + lg * 4);
            *(uint2*)(aHi + o) = make_uint2(ph0, ph1);
            *(uint2*)(aLo + o) = make_uint2(pl0, pl1);
        }
    }
}

__global__ void __launch_bounds__(384, 1)
k2_main(const void* __restrict__ ei, const float* __restrict__ b3,
        float* __restrict__ out, int E, int ntiles) {
    extern __shared__ char dsm[];
    u32 braw = smem_u32(dsm);
    u32 base = (braw + 1023u) & ~1023u;
    char* sm = dsm + (base - braw);

    int tid  = threadIdx.x;
    int wid  = tid >> 5, lane = tid & 31;
    int is64 = g_is64;
    const long long* p64 = (const long long*)ei;
    const int*       p32 = (const int*)ei;

    const float2* swb = (const float2*)(sm + OFF_SWB);
    float* sred = (float*)(sm + OFF_SRED);

    // stage W2' bf16 hi/lo + w3b2 into smem (all 384 threads)
    {
        uint4* dh = (uint4*)(sm + OFF_WHI);
        uint4* dl = (uint4*)(sm + OFF_WLO);
        const uint4* shi = (const uint4*)g_Whi;
        const uint4* slo = (const uint4*)g_Wlo;
        for (int i = tid; i < 2048; i += 384) { dh[i] = shi[i]; dl[i] = slo[i]; }
        if (tid < HID) ((float2*)(sm + OFF_SWB))[tid] = g_w3b2[tid];
    }
    float bias3 = b3[0];
    u32 wHiB = base + OFF_WHI, wLoB = base + OFF_WLO;

    // consumer constants: warp tile = m 64 (wm 0..1) x n 32 (wn 0..3)
    int wm = (wid >> 2) & 1, wn = wid & 3;
    int li = lane & 7, grp = lane >> 3;
    int kgA = (grp >> 1) * 8;
    int kgB = (grp & 1) * 8;
    int nB0 = 32 * wn + (grp >> 1) * 8 + li;
    int nB1 = nB0 + 16;
    int bq0 = ((nB0 >> 3) << 10) + ((nB0 & 7) << 7);
    int bq1 = ((nB1 >> 3) << 10) + ((nB1 & 7) << 7);
    // A row-part per mt (4 x m16 tiles)
    int rp[4];
#pragma unroll
    for (int mt = 0; mt < 4; mt++) {
        int rA = wm * 64 + mt * 16 + (grp & 1) * 8 + li;
        rp[mt] = ((rA >> 3) << 10) + ((rA & 7) << 7);
    }

    // producer constants
    int tid_p = tid - 256;
    int lg = tid_p & 7, gr = tid_p >> 3;
    float4 dq[4];
    if (wid >= 8) {
#pragma unroll
        for (int i = 0; i < 4; i++) dq[i] = ((const float4*)g_d)[i * 8 + lg];
    }

    __syncthreads();  // W, swb staged

    // prologue: producers fill buf0 with this block's first tile
    int first = blockIdx.x;
    if (wid >= 8 && first < ntiles)
        k2_produce(first, E, is64, p64, p32, dq,
                   sm + OFF_H(0, 0), sm + OFF_H(0, 1), lg, gr);

    int iter = 0;
    for (int tile = first; tile < ntiles; tile += gridDim.x, iter++) {
        int buf = iter & 1;
        __syncthreads();  // H[buf] ready; H[buf^1] free; sred(prev) consumed by producers

        if (wid < 8) {
            // ============ CONSUMERS: fused 3-pass MMA, m64 x n32 per warp ============
            u32 hHiB = base + OFF_H(buf, 0);
            u32 hLoB = base + OFF_H(buf, 1);

            float acc[4][4][4];
#pragma unroll
            for (int mt = 0; mt < 4; mt++)
#pragma unroll
                for (int nt = 0; nt < 4; nt++)
#pragma unroll
                    for (int q = 0; q < 4; q++) acc[mt][nt][q] = 0.f;

#pragma unroll 1
            for (int ks = 0; ks < 8; ks++) {
                int k0 = ks * 16;
                int kkA = k0 + kgA;
                int kpA = ((kkA >> 6) << 14) + ((kkA & 63) << 1);
                int kkB = k0 + kgB;
                int kpB = ((kkB >> 6) << 14) + ((kkB & 63) << 1);
                int oB0 = bq0 + kpB; oB0 ^= ((oB0 >> 3) & 0x70);
                int oB1 = bq1 + kpB; oB1 ^= ((oB1 >> 3) & 0x70);

                u32 bh0[4], bh1[4], bl0[4], bl1[4];
                ldsm4(bh0, wHiB + (u32)oB0);
                ldsm4(bh1, wHiB + (u32)oB1);
                ldsm4(bl0, wLoB + (u32)oB0);
                ldsm4(bl1, wLoB + (u32)oB1);

                u32 aH[4][4], aL[4][4];
#pragma unroll
                for (int mt = 0; mt < 4; mt++) {
                    int oA = rp[mt] + kpA; oA ^= ((oA >> 3) & 0x70);
                    ldsm4(aH[mt], hHiB + (u32)oA);
                    ldsm4(aL[mt], hLoB + (u32)oA);
                }

                // pass-major ordering: acc reuse distance = 16 MMAs
#pragma unroll
                for (int mt = 0; mt < 4; mt++) {           // hi x hi
                    mma16816(acc[mt][0], aH[mt], bh0[0], bh0[1]);
                    mma16816(acc[mt][1], aH[mt], bh0[2], bh0[3]);
                    mma16816(acc[mt][2], aH[mt], bh1[0], bh1[1]);
                    mma16816(acc[mt][3], aH[mt], bh1[2], bh1[3]);
                }
#pragma unroll
                for (int mt = 0; mt < 4; mt++) {           // hi x lo
                    mma16816(acc[mt][0], aH[mt], bl0[0], bl0[1]);
                    mma16816(acc[mt][1], aH[mt], bl0[2], bl0[3]);
                    mma16816(acc[mt][2], aH[mt], bl1[0], bl1[1]);
                    mma16816(acc[mt][3], aH[mt], bl1[2], bl1[3]);
                }
#pragma unroll
                for (int mt = 0; mt < 4; mt++) {           // lo x hi
                    mma16816(acc[mt][0], aL[mt], bh0[0], bh0[1]);
                    mma16816(acc[mt][1], aL[mt], bh0[2], bh0[3]);
                    mma16816(acc[mt][2], aL[mt], bh1[0], bh1[1]);
                    mma16816(acc[mt][3], aL[mt], bh1[2], bh1[3]);
                }
            }

            // epilogue (consumer part): relu(acc + b2') . w3, quad-reduce, stash partials
#pragma unroll
            for (int mt = 0; mt < 4; mt++) {
                float pl = 0.f, ph = 0.f;
#pragma unroll
                for (int nt = 0; nt < 4; nt++)
#pragma unroll
                    for (int cp = 0; cp < 2; cp++) {
                        float2 w = swb[32 * wn + nt * 8 + 2 * (lane & 3) + cp];
                        pl = fmaf(fmaxf(acc[mt][nt][cp]     + w.x, 0.f), w.y, pl);
                        ph = fmaf(fmaxf(acc[mt][nt][2 + cp] + w.x, 0.f), w.y, ph);
                    }
                pl += __shfl_xor_sync(0xffffffffu, pl, 1);
                pl += __shfl_xor_sync(0xffffffffu, pl, 2);
                ph += __shfl_xor_sync(0xffffffffu, ph, 1);
                ph += __shfl_xor_sync(0xffffffffu, ph, 2);
                if ((lane & 3) == 0) {
                    int r = wm * 64 + mt * 16 + (lane >> 2);
                    sred[wn * 128 + r]     = pl;
                    sred[wn * 128 + r + 8] = ph;
                }
            }
            // non-blocking arrive: producers pick up the final sum + store
            asm volatile("bar.arrive 1, 384;" ::: "memory");
        } else {
            // ============ PRODUCERS: transform tile+grid into H[buf^1], then output epilogue ============
            int nt = tile + gridDim.x;
            if (nt < ntiles)
                k2_produce(nt, E, is64, p64, p32, dq,
                           sm + OFF_H(buf ^ 1, 0), sm + OFF_H(buf ^ 1, 1), lg, gr);

            asm volatile("bar.sync 1, 384;" ::: "memory");  // wait for consumer sred
            long long ge = (long long)tile * TM + tid_p;
            if (ge < E) {
                float v = sred[tid_p] + sred[128 + tid_p] + sred[256 + tid_p] + sred[384 + tid_p];
                out[ge] = v + bias3;
            }
        }
    }
}

// ---------------- launch ----------------
extern "C" void kernel_launch(void* const* d_in, const int* in_sizes, int n_in,
                              void* d_out, int out_size) {
    const float* z     = (const float*)d_in[0];
    const void*  ei    = d_in[1];
    const float* c     = (const float*)d_in[2];
    const float* W1    = (const float*)d_in[3];
    const float* b1    = (const float*)d_in[4];
    const float* gamma = (const float*)d_in[5];
    const float* beta  = (const float*)d_in[6];
    const float* W2    = (const float*)d_in[7];
    const float* b2    = (const float*)d_in[8];
    const float* W3    = (const float*)d_in[9];
    const float* b3    = (const float*)d_in[10];
    float* out = (float*)d_out;

    int N = in_sizes[0] / ZD;
    int E = in_sizes[1] / 2;

    cudaFuncSetAttribute(k2_main, cudaFuncAttributeMaxDynamicSharedMemorySize, K2_SMEM);

    k0_nodes<<<(N + NPB - 1) / NPB + 1, 128>>>(z, W1, N, (const unsigned int*)ei, c, b1);
    k1_stats<<<K1_BLOCKS, 128>>>(ei, E);
    k15_fold<<<HID, 128>>>(gamma, beta, W2, b2, W3, 1.0 / (double)E);
    int ntiles = (E + TM - 1) / TM;
    k2_main<<<K2_GRID, 384, K2_SMEM>>>(ei, b3, out, E, ntiles);
}

// round 15
// speedup vs baseline: 1.1728x; 1.1728x over previous
#include <cuda_runtime.h>
#include <cuda_bf16.h>
#include <stdint.h>

#define NODES_MAX 50000
#define HID 128
#define ZD 64
#define NPB 16          // nodes per block in K0
#define TM 128          // edges per tile in K2
#define K1_BLOCKS 1184  // 148 SMs * 8
#define K2_GRID 148

typedef unsigned long long u64;
typedef unsigned int u32;

// ---------------- static device scratch ----------------
__device__ float  g_A[NODES_MAX * HID];     // z @ W1[0:64]
__device__ float  g_B[NODES_MAX * HID];     // z @ W1[64:128]
__device__ float  g_d[HID];                 // c @ W1[128:132] + b1
__device__ double g_sum[HID];
__device__ double g_sumsq[HID];
__device__ unsigned short g_Whi[16384];     // BN-folded W2 bf16-hi, MMA swizzled layout
__device__ unsigned short g_Wlo[16384];     // bf16-lo residual
__device__ float2 g_w3b2[HID];              // (b2_folded, w3) per feature
__device__ int    g_is64;

// ---------------- helpers ----------------
__device__ __forceinline__ u32 smem_u32(const void* p) {
    u32 a;
    asm("{ .reg .u64 t; cvta.to.shared.u64 t, %1; cvt.u32.u64 %0, t; }" : "=r"(a) : "l"(p));
    return a;
}
// packed bf16x2 convert: low half <- lo, high half <- hi
__device__ __forceinline__ u32 bf2(float lo, float hi) {
    u32 r;
    asm("cvt.rn.bf16x2.f32 %0, %1, %2;" : "=r"(r) : "f"(hi), "f"(lo));
    return r;
}
__device__ __forceinline__ void ldsm4(u32* r, u32 addr) {
    asm volatile("ldmatrix.sync.aligned.m8n8.x4.shared.b16 {%0,%1,%2,%3}, [%4];"
                 : "=r"(r[0]), "=r"(r[1]), "=r"(r[2]), "=r"(r[3]) : "r"(addr));
}
__device__ __forceinline__ void mma16816(float* c, const u32* a, u32 b0, u32 b1) {
    asm volatile(
        "mma.sync.aligned.m16n8k16.row.col.f32.bf16.bf16.f32 "
        "{%0,%1,%2,%3}, {%4,%5,%6,%7}, {%8,%9}, {%0,%1,%2,%3};"
        : "+f"(c[0]), "+f"(c[1]), "+f"(c[2]), "+f"(c[3])
        : "r"(a[0]), "r"(a[1]), "r"(a[2]), "r"(a[3]), "r"(b0), "r"(b1));
}

// MMA-layout byte offset for element (row r, col k) in a 128x128 bf16 K-major
// SW128 blocked-atom tile: atom = 8 rows x 64 bf16 (1024B), 16 atom-rows x 2 atom-cols.
__device__ __forceinline__ int bofs(int r, int k) {
    int off = ((r >> 3) << 10) + ((k >> 6) << 14) + ((r & 7) << 7) + ((k & 63) << 1);
    return off ^ ((off >> 3) & 0x70);
}

// ---------------- K0: per-node partial products (+fused detect & k0b in extra block) ----------------
__global__ void k0_nodes(const float* __restrict__ z, const float* __restrict__ W1, int N,
                         const unsigned int* __restrict__ eiw,
                         const float* __restrict__ c, const float* __restrict__ b1) {
    __shared__ float zs[NPB * ZD];
    int tid = threadIdx.x;

    if (blockIdx.x == gridDim.x - 1) {
        // --- fused k_detect: is edge_index int64 or int32? ---
        __shared__ int nz;
        if (tid == 0) nz = 0;
        __syncthreads();
        if (eiw[2 * tid + 1] != 0u) atomicAdd(&nz, 1);
        __syncthreads();
        if (tid == 0) g_is64 = (nz == 0) ? 1 : 0;
        // --- fused k0b: d = c@W1c + b1, zero BN accumulators ---
        float v = b1[tid];
#pragma unroll
        for (int k = 0; k < 4; k++) v = fmaf(c[k], W1[(2 * ZD + k) * HID + tid], v);
        g_d[tid]     = v;
        g_sum[tid]   = 0.0;
        g_sumsq[tid] = 0.0;
        return;
    }

    int base = blockIdx.x * NPB;
    int nn   = N - base; if (nn > NPB) nn = NPB;

    for (int i = tid; i < nn * ZD; i += 128) zs[i] = z[base * ZD + i];
    __syncthreads();

    float a[NPB], b[NPB];
#pragma unroll
    for (int n = 0; n < NPB; n++) { a[n] = 0.f; b[n] = 0.f; }

#pragma unroll 8
    for (int k = 0; k < ZD; k++) {
        float ws = W1[k * HID + tid];
        float wd = W1[(ZD + k) * HID + tid];
#pragma unroll
        for (int n = 0; n < NPB; n++) {
            float zk = zs[n * ZD + k];
            a[n] = fmaf(zk, ws, a[n]);
            b[n] = fmaf(zk, wd, b[n]);
        }
    }
    for (int n = 0; n < nn; n++) {
        g_A[(base + n) * HID + tid] = a[n];
        g_B[(base + n) * HID + tid] = b[n];
    }
}

// ---------------- K1: BN statistics pass — warp-per-edge float4 gather ----------------
// lane = feature quad (fq: features 4*fq..4*fq+3), warp (eq) strides over edge quads.
// One LDG.128 per row per warp (was 4+4 slice LDG.32s); indices vectorized 4x.
template<bool IS64>
__device__ __forceinline__ void k1_body(const void* __restrict__ ei, int E, int per) {
    int tid = threadIdx.x;
    int fq = tid & 31, eq = tid >> 5;
    int e0 = blockIdx.x * per;
    int e1 = e0 + per; if (e1 > E) e1 = E;

    const float4* A4 = (const float4*)g_A;   // row stride = 32 float4
    const float4* B4 = (const float4*)g_B;
    float4 dv = ((const float4*)g_d)[fq];
    float4 S1 = make_float4(0.f, 0.f, 0.f, 0.f);
    float4 S2 = make_float4(0.f, 0.f, 0.f, 0.f);

    const int*       p32 = (const int*)ei;
    const long long* p64 = (const long long*)ei;
    int n4 = (e1 > e0) ? ((e1 - e0) >> 2) : 0;

    for (int q = eq; q < n4; q += 4) {
        int ebase = e0 + q * 4;
        int s[4], t[4];
        if (IS64) {
            longlong2 sa = *(const longlong2*)(p64 + ebase);
            longlong2 sb = *(const longlong2*)(p64 + ebase + 2);
            longlong2 ta = *(const longlong2*)(p64 + (long long)E + ebase);
            longlong2 tb = *(const longlong2*)(p64 + (long long)E + ebase + 2);
            s[0] = (int)sa.x; s[1] = (int)sa.y; s[2] = (int)sb.x; s[3] = (int)sb.y;
            t[0] = (int)ta.x; t[1] = (int)ta.y; t[2] = (int)tb.x; t[3] = (int)tb.y;
        } else {
            int4 si = *(const int4*)(p32 + ebase);
            int4 ti = *(const int4*)(p32 + (long long)E + ebase);
            s[0] = si.x; s[1] = si.y; s[2] = si.z; s[3] = si.w;
            t[0] = ti.x; t[1] = ti.y; t[2] = ti.z; t[3] = ti.w;
        }
        float4 a[4], b[4];
#pragma unroll
        for (int j = 0; j < 4; j++) a[j] = A4[s[j] * 32 + fq];
#pragma unroll
        for (int j = 0; j < 4; j++) b[j] = B4[t[j] * 32 + fq];
#pragma unroll
        for (int j = 0; j < 4; j++) {
            float h0 = fmaxf(a[j].x + b[j].x + dv.x, 0.f);
            float h1 = fmaxf(a[j].y + b[j].y + dv.y, 0.f);
            float h2 = fmaxf(a[j].z + b[j].z + dv.z, 0.f);
            float h3 = fmaxf(a[j].w + b[j].w + dv.w, 0.f);
            S1.x += h0; S1.y += h1; S1.z += h2; S1.w += h3;
            S2.x = fmaf(h0, h0, S2.x); S2.y = fmaf(h1, h1, S2.y);
            S2.z = fmaf(h2, h2, S2.z); S2.w = fmaf(h3, h3, S2.w);
        }
    }
    // scalar tail (at most 3 edges)
    for (int e = e0 + n4 * 4 + eq; e < e1; e += 4) {
        int s = IS64 ? (int)p64[e] : p32[e];
        int t = IS64 ? (int)p64[(long long)E + e] : p32[(long long)E + e];
        float4 a = A4[s * 32 + fq], b = B4[t * 32 + fq];
        float h0 = fmaxf(a.x + b.x + dv.x, 0.f);
        float h1 = fmaxf(a.y + b.y + dv.y, 0.f);
        float h2 = fmaxf(a.z + b.z + dv.z, 0.f);
        float h3 = fmaxf(a.w + b.w + dv.w, 0.f);
        S1.x += h0; S1.y += h1; S1.z += h2; S1.w += h3;
        S2.x = fmaf(h0, h0, S2.x); S2.y = fmaf(h1, h1, S2.y);
        S2.z = fmaf(h2, h2, S2.z); S2.w = fmaf(h3, h3, S2.w);
    }

    // block reduction across the 4 eq-warps, then one atomic per feature
    __shared__ float sm1[4][HID], sm2[4][HID];
    sm1[eq][fq * 4 + 0] = S1.x; sm1[eq][fq * 4 + 1] = S1.y;
    sm1[eq][fq * 4 + 2] = S1.z; sm1[eq][fq * 4 + 3] = S1.w;
    sm2[eq][fq * 4 + 0] = S2.x; sm2[eq][fq * 4 + 1] = S2.y;
    sm2[eq][fq * 4 + 2] = S2.z; sm2[eq][fq * 4 + 3] = S2.w;
    __syncthreads();
    float v1 = sm1[0][tid] + sm1[1][tid] + sm1[2][tid] + sm1[3][tid];
    float v2 = sm2[0][tid] + sm2[1][tid] + sm2[2][tid] + sm2[3][tid];
    atomicAdd(&g_sum[tid],   (double)v1);
    atomicAdd(&g_sumsq[tid], (double)v2);
}

__global__ void __launch_bounds__(128, 8) k1_stats(const void* __restrict__ ei, int E, int per) {
    if (g_is64) k1_body<true>(ei, E, per);
    else        k1_body<false>(ei, E, per);
}

// ---------------- K1.5: fold BN into W2 (PARALLEL: 128 blocks, one per output feature) ----------------
__global__ void k15_fold(const float* __restrict__ gamma, const float* __restrict__ beta,
                         const float* __restrict__ W2, const float* __restrict__ b2,
                         const float* __restrict__ W3, double invE) {
    __shared__ float red[4];
    int i = blockIdx.x;    // output feature f
    int k = threadIdx.x;   // input feature k
    int lane = k & 31, wrp = k >> 5;

    double m = g_sum[k] * invE;
    double v = g_sumsq[k] * invE - m * m;
    float x = (float)v + 1e-5f;
    float s = rsqrtf(x);
    s = s * (1.5f - 0.5f * x * s * s);  // Newton refine
    float g = s * gamma[k];
    float gsc_k = g;
    float gsh_k = beta[k] - (float)m * g;

    float w = W2[k * HID + i];           // W2[k][f=i]
    float wf = gsc_k * w;                // BN scale folded
    __nv_bfloat16 hb = __float2bfloat16(wf);
    float hf = __bfloat162float(hb);
    __nv_bfloat16 lb = __float2bfloat16(wf - hf);
    int o = bofs(i, k) >> 1;             // row = feature f, col = k
    g_Whi[o] = *(const unsigned short*)&hb;
    g_Wlo[o] = *(const unsigned short*)&lb;

    float bb = gsh_k * w;
#pragma unroll
    for (int d = 16; d > 0; d >>= 1) bb += __shfl_xor_sync(0xffffffffu, bb, d);
    if (lane == 0) red[wrp] = bb;
    __syncthreads();
    if (k == 0) {
        float tot = red[0] + red[1] + red[2] + red[3];
        g_w3b2[i] = make_float2(b2[i] + tot, W3[i]);
    }
}

// ---------------- K2: warp-specialized producer/consumer ----------------
// 384 threads: warps 0-7 = MMA consumers (each m=64 x n=32),
// warps 8-11 = pipelined gather producers + output epilogue.
// smem (1024-aligned base):
#define OFF_WHI 0
#define OFF_WLO 32768
#define OFF_H(buf, part) (65536 + (buf) * 65536 + (part) * 32768)
#define OFF_SWB 196608          // w3b2 float2[128] (1KB)
#define OFF_SRED 197632         // sred[4][128] floats
#define K2_SMEM (199680 + 1024)

// producer: coalesced gather + relu + bf16 hi/lo split, SOFTWARE-PIPELINED.
static __device__ __forceinline__ void k2_produce(
    int tile, long long E, int is64, const long long* p64, const int* p32,
    const float4* dq, char* aHi, char* aLo, int lg, int gr)
{
    int sa[8], ta[8];
#pragma unroll
    for (int p = 0; p < 8; p++) {
        long long ge = (long long)tile * TM + p * 16 + gr;
        long long g2 = (ge < E) ? ge : (long long)0;
        sa[p] = is64 ? (int)p64[g2] : p32[g2];
        ta[p] = is64 ? (int)p64[E + g2] : p32[E + g2];
    }

    float4 av[2][4], bv[2][4];
    {
        const float4* ap = (const float4*)(g_A + (size_t)sa[0] * HID) + lg;
        const float4* bp = (const float4*)(g_B + (size_t)ta[0] * HID) + lg;
#pragma unroll
        for (int i = 0; i < 4; i++) av[0][i] = ap[i * 8];
#pragma unroll
        for (int i = 0; i < 4; i++) bv[0][i] = bp[i * 8];
    }

#pragma unroll
    for (int p = 0; p < 8; p++) {
        int cur = p & 1;
        if (p < 7) {
            const float4* ap = (const float4*)(g_A + (size_t)sa[p + 1] * HID) + lg;
            const float4* bp = (const float4*)(g_B + (size_t)ta[p + 1] * HID) + lg;
#pragma unroll
            for (int i = 0; i < 4; i++) av[cur ^ 1][i] = ap[i * 8];
#pragma unroll
            for (int i = 0; i < 4; i++) bv[cur ^ 1][i] = bp[i * 8];
        }
        int r = p * 16 + gr;
#pragma unroll
        for (int i = 0; i < 4; i++) {
            float4 d = dq[i];
            float4 a = av[cur][i], b = bv[cur][i];
            float h0 = fmaxf(a.x + b.x + d.x, 0.f);
            float h1 = fmaxf(a.y + b.y + d.y, 0.f);
            float h2 = fmaxf(a.z + b.z + d.z, 0.f);
            float h3 = fmaxf(a.w + b.w + d.w, 0.f);
            u32 ph0 = bf2(h0, h1), ph1 = bf2(h2, h3);
            float r00 = __uint_as_float(ph0 << 16);
            float r01 = __uint_as_float(ph0 & 0xFFFF0000u);
            float r10 = __uint_as_float(ph1 << 16);
            float r11 = __uint_as_float(ph1 & 0xFFFF0000u);
            u32 pl0 = bf2(h0 - r00, h1 - r01);
            u32 pl1 = bf2(h2 - r10, h3 - r11);
            int o = bofs(r, i * 32 + lg * 4);
            *(uint2*)(aHi + o) = make_uint2(ph0, ph1);
            *(uint2*)(aLo + o) = make_uint2(pl0, pl1);
        }
    }
}

__global__ void __launch_bounds__(384, 1)
k2_main(const void* __restrict__ ei, const float* __restrict__ b3,
        float* __restrict__ out, int E, int ntiles) {
    extern __shared__ char dsm[];
    u32 braw = smem_u32(dsm);
    u32 base = (braw + 1023u) & ~1023u;
    char* sm = dsm + (base - braw);

    int tid  = threadIdx.x;
    int wid  = tid >> 5, lane = tid & 31;
    int is64 = g_is64;
    const long long* p64 = (const long long*)ei;
    const int*       p32 = (const int*)ei;

    const float2* swb = (const float2*)(sm + OFF_SWB);
    float* sred = (float*)(sm + OFF_SRED);

    // stage W2' bf16 hi/lo + w3b2 into smem (all 384 threads)
    {
        uint4* dh = (uint4*)(sm + OFF_WHI);
        uint4* dl = (uint4*)(sm + OFF_WLO);
        const uint4* shi = (const uint4*)g_Whi;
        const uint4* slo = (const uint4*)g_Wlo;
        for (int i = tid; i < 2048; i += 384) { dh[i] = shi[i]; dl[i] = slo[i]; }
        if (tid < HID) ((float2*)(sm + OFF_SWB))[tid] = g_w3b2[tid];
    }
    float bias3 = b3[0];
    u32 wHiB = base + OFF_WHI, wLoB = base + OFF_WLO;

    // consumer constants: warp tile = m 64 (wm 0..1) x n 32 (wn 0..3)
    int wm = (wid >> 2) & 1, wn = wid & 3;
    int li = lane & 7, grp = lane >> 3;
    int kgA = (grp >> 1) * 8;
    int kgB = (grp & 1) * 8;
    int nB0 = 32 * wn + (grp >> 1) * 8 + li;
    int nB1 = nB0 + 16;
    int bq0 = ((nB0 >> 3) << 10) + ((nB0 & 7) << 7);
    int bq1 = ((nB1 >> 3) << 10) + ((nB1 & 7) << 7);
    // A row-part per mt (4 x m16 tiles)
    int rp[4];
#pragma unroll
    for (int mt = 0; mt < 4; mt++) {
        int rA = wm * 64 + mt * 16 + (grp & 1) * 8 + li;
        rp[mt] = ((rA >> 3) << 10) + ((rA & 7) << 7);
    }

    // producer constants
    int tid_p = tid - 256;
    int lg = tid_p & 7, gr = tid_p >> 3;
    float4 dq[4];
    if (wid >= 8) {
#pragma unroll
        for (int i = 0; i < 4; i++) dq[i] = ((const float4*)g_d)[i * 8 + lg];
    }

    __syncthreads();  // W, swb staged

    // prologue: producers fill buf0 with this block's first tile
    int first = blockIdx.x;
    if (wid >= 8 && first < ntiles)
        k2_produce(first, E, is64, p64, p32, dq,
                   sm + OFF_H(0, 0), sm + OFF_H(0, 1), lg, gr);

    int iter = 0;
    for (int tile = first; tile < ntiles; tile += gridDim.x, iter++) {
        int buf = iter & 1;
        __syncthreads();  // H[buf] ready; H[buf^1] free; sred(prev) consumed by producers

        if (wid < 8) {
            // ============ CONSUMERS: fused 3-pass MMA, m64 x n32 per warp ============
            u32 hHiB = base + OFF_H(buf, 0);
            u32 hLoB = base + OFF_H(buf, 1);

            float acc[4][4][4];
#pragma unroll
            for (int mt = 0; mt < 4; mt++)
#pragma unroll
                for (int nt = 0; nt < 4; nt++)
#pragma unroll
                    for (int q = 0; q < 4; q++) acc[mt][nt][q] = 0.f;

#pragma unroll 1
            for (int ks = 0; ks < 8; ks++) {
                int k0 = ks * 16;
                int kkA = k0 + kgA;
                int kpA = ((kkA >> 6) << 14) + ((kkA & 63) << 1);
                int kkB = k0 + kgB;
                int kpB = ((kkB >> 6) << 14) + ((kkB & 63) << 1);
                int oB0 = bq0 + kpB; oB0 ^= ((oB0 >> 3) & 0x70);
                int oB1 = bq1 + kpB; oB1 ^= ((oB1 >> 3) & 0x70);

                u32 bh0[4], bh1[4], bl0[4], bl1[4];
                ldsm4(bh0, wHiB + (u32)oB0);
                ldsm4(bh1, wHiB + (u32)oB1);
                ldsm4(bl0, wLoB + (u32)oB0);
                ldsm4(bl1, wLoB + (u32)oB1);

                u32 aH[4][4], aL[4][4];
#pragma unroll
                for (int mt = 0; mt < 4; mt++) {
                    int oA = rp[mt] + kpA; oA ^= ((oA >> 3) & 0x70);
                    ldsm4(aH[mt], hHiB + (u32)oA);
                    ldsm4(aL[mt], hLoB + (u32)oA);
                }

                // pass-major ordering: acc reuse distance = 16 MMAs
#pragma unroll
                for (int mt = 0; mt < 4; mt++) {           // hi x hi
                    mma16816(acc[mt][0], aH[mt], bh0[0], bh0[1]);
                    mma16816(acc[mt][1], aH[mt], bh0[2], bh0[3]);
                    mma16816(acc[mt][2], aH[mt], bh1[0], bh1[1]);
                    mma16816(acc[mt][3], aH[mt], bh1[2], bh1[3]);
                }
#pragma unroll
                for (int mt = 0; mt < 4; mt++) {           // hi x lo
                    mma16816(acc[mt][0], aH[mt], bl0[0], bl0[1]);
                    mma16816(acc[mt][1], aH[mt], bl0[2], bl0[3]);
                    mma16816(acc[mt][2], aH[mt], bl1[0], bl1[1]);
                    mma16816(acc[mt][3], aH[mt], bl1[2], bl1[3]);
                }
#pragma unroll
                for (int mt = 0; mt < 4; mt++) {           // lo x hi
                    mma16816(acc[mt][0], aL[mt], bh0[0], bh0[1]);
                    mma16816(acc[mt][1], aL[mt], bh0[2], bh0[3]);
                    mma16816(acc[mt][2], aL[mt], bh1[0], bh1[1]);
                    mma16816(acc[mt][3], aL[mt], bh1[2], bh1[3]);
                }
            }

            // epilogue (consumer part): relu(acc + b2') . w3, quad-reduce, stash partials
#pragma unroll
            for (int mt = 0; mt < 4; mt++) {
                float pl = 0.f, ph = 0.f;
#pragma unroll
                for (int nt = 0; nt < 4; nt++)
#pragma unroll
                    for (int cp = 0; cp < 2; cp++) {
                        float2 w = swb[32 * wn + nt * 8 + 2 * (lane & 3) + cp];
                        pl = fmaf(fmaxf(acc[mt][nt][cp]     + w.x, 0.f), w.y, pl);
                        ph = fmaf(fmaxf(acc[mt][nt][2 + cp] + w.x, 0.f), w.y, ph);
                    }
                pl += __shfl_xor_sync(0xffffffffu, pl, 1);
                pl += __shfl_xor_sync(0xffffffffu, pl, 2);
                ph += __shfl_xor_sync(0xffffffffu, ph, 1);
                ph += __shfl_xor_sync(0xffffffffu, ph, 2);
                if ((lane & 3) == 0) {
                    int r = wm * 64 + mt * 16 + (lane >> 2);
                    sred[wn * 128 + r]     = pl;
                    sred[wn * 128 + r + 8] = ph;
                }
            }
            // non-blocking arrive: producers pick up the final sum + store
            asm volatile("bar.arrive 1, 384;" ::: "memory");
        } else {
            // ============ PRODUCERS: transform tile+grid into H[buf^1], then output epilogue ============
            int nt = tile + gridDim.x;
            if (nt < ntiles)
                k2_produce(nt, E, is64, p64, p32, dq,
                           sm + OFF_H(buf ^ 1, 0), sm + OFF_H(buf ^ 1, 1), lg, gr);

            asm volatile("bar.sync 1, 384;" ::: "memory");  // wait for consumer sred
            long long ge = (long long)tile * TM + tid_p;
            if (ge < E) {
                float v = sred[tid_p] + sred[128 + tid_p] + sred[256 + tid_p] + sred[384 + tid_p];
                out[ge] = v + bias3;
            }
        }
    }
}

// ---------------- launch ----------------
extern "C" void kernel_launch(void* const* d_in, const int* in_sizes, int n_in,
                              void* d_out, int out_size) {
    const float* z     = (const float*)d_in[0];
    const void*  ei    = d_in[1];
    const float* c     = (const float*)d_in[2];
    const float* W1    = (const float*)d_in[3];
    const float* b1    = (const float*)d_in[4];
    const float* gamma = (const float*)d_in[5];
    const float* beta  = (const float*)d_in[6];
    const float* W2    = (const float*)d_in[7];
    const float* b2    = (const float*)d_in[8];
    const float* W3    = (const float*)d_in[9];
    const float* b3    = (const float*)d_in[10];
    float* out = (float*)d_out;

    int N = in_sizes[0] / ZD;
    int E = in_sizes[1] / 2;

    cudaFuncSetAttribute(k2_main, cudaFuncAttributeMaxDynamicSharedMemorySize, K2_SMEM);

    k0_nodes<<<(N + NPB - 1) / NPB + 1, 128>>>(z, W1, N, (const unsigned int*)ei, c, b1);
    int per = (((E + K1_BLOCKS - 1) / K1_BLOCKS) + 3) & ~3;   // 4-aligned per-block edge range
    k1_stats<<<K1_BLOCKS, 128>>>(ei, E, per);
    k15_fold<<<HID, 128>>>(gamma, beta, W2, b2, W3, 1.0 / (double)E);
    int ntiles = (E + TM - 1) / TM;
    k2_main<<<K2_GRID, 384, K2_SMEM>>>(ei, b3, out, E, ntiles);
}

// round 16
// speedup vs baseline: 1.4237x; 1.2139x over previous
#include <cuda_runtime.h>
#include <cuda_bf16.h>
#include <cuda_fp16.h>
#include <stdint.h>

#define NODES_MAX 50000
#define HID 128
#define ZD 64
#define NPB 16          // nodes per block in K0
#define TM 128          // edges per tile in K2
#define K1_BLOCKS 1184  // 148 SMs * 8
#define K2_GRID 148

typedef unsigned long long u64;
typedef unsigned int u32;

// ---------------- static device scratch ----------------
__device__ float  g_A[NODES_MAX * HID];     // z @ W1[0:64]
__device__ float  g_B[NODES_MAX * HID];     // z @ W1[64:128]
__device__ float  g_d[HID];                 // c @ W1[128:132] + b1
__device__ double g_sum[HID];
__device__ double g_sumsq[HID];
__device__ unsigned short g_Whi[16384];     // BN-folded W2 fp16-hi, MMA swizzled layout
__device__ unsigned short g_Wlo[16384];     // fp16-lo residual
__device__ float2 g_w3b2[HID];              // (b2_folded, w3) per feature
__device__ int    g_is64;

// ---------------- helpers ----------------
__device__ __forceinline__ u32 smem_u32(const void* p) {
    u32 a;
    asm("{ .reg .u64 t; cvta.to.shared.u64 t, %1; cvt.u32.u64 %0, t; }" : "=r"(a) : "l"(p));
    return a;
}
// packed fp16x2 convert: low half <- lo, high half <- hi
__device__ __forceinline__ u32 hf2(float lo, float hi) {
    u32 r;
    asm("cvt.rn.f16x2.f32 %0, %1, %2;" : "=r"(r) : "f"(hi), "f"(lo));
    return r;
}
__device__ __forceinline__ void ldsm4(u32* r, u32 addr) {
    asm volatile("ldmatrix.sync.aligned.m8n8.x4.shared.b16 {%0,%1,%2,%3}, [%4];"
                 : "=r"(r[0]), "=r"(r[1]), "=r"(r[2]), "=r"(r[3]) : "r"(addr));
}
__device__ __forceinline__ void mma16816(float* c, const u32* a, u32 b0, u32 b1) {
    asm volatile(
        "mma.sync.aligned.m16n8k16.row.col.f32.f16.f16.f32 "
        "{%0,%1,%2,%3}, {%4,%5,%6,%7}, {%8,%9}, {%0,%1,%2,%3};"
        : "+f"(c[0]), "+f"(c[1]), "+f"(c[2]), "+f"(c[3])
        : "r"(a[0]), "r"(a[1]), "r"(a[2]), "r"(a[3]), "r"(b0), "r"(b1));
}

// MMA-layout byte offset for element (row r, col k) in a 128x128 fp16 K-major
// SW128 blocked-atom tile: atom = 8 rows x 64 fp16 (1024B), 16 atom-rows x 2 atom-cols.
__device__ __forceinline__ int bofs(int r, int k) {
    int off = ((r >> 3) << 10) + ((k >> 6) << 14) + ((r & 7) << 7) + ((k & 63) << 1);
    return off ^ ((off >> 3) & 0x70);
}

// ---------------- K0: per-node partial products (+fused detect & k0b in extra block) ----------------
__global__ void k0_nodes(const float* __restrict__ z, const float* __restrict__ W1, int N,
                         const unsigned int* __restrict__ eiw,
                         const float* __restrict__ c, const float* __restrict__ b1) {
    __shared__ float zs[NPB * ZD];
    int tid = threadIdx.x;

    if (blockIdx.x == gridDim.x - 1) {
        // --- fused k_detect: is edge_index int64 or int32? ---
        __shared__ int nz;
        if (tid == 0) nz = 0;
        __syncthreads();
        if (eiw[2 * tid + 1] != 0u) atomicAdd(&nz, 1);
        __syncthreads();
        if (tid == 0) g_is64 = (nz == 0) ? 1 : 0;
        // --- fused k0b: d = c@W1c + b1, zero BN accumulators ---
        float v = b1[tid];
#pragma unroll
        for (int k = 0; k < 4; k++) v = fmaf(c[k], W1[(2 * ZD + k) * HID + tid], v);
        g_d[tid]     = v;
        g_sum[tid]   = 0.0;
        g_sumsq[tid] = 0.0;
        return;
    }

    int base = blockIdx.x * NPB;
    int nn   = N - base; if (nn > NPB) nn = NPB;

    for (int i = tid; i < nn * ZD; i += 128) zs[i] = z[base * ZD + i];
    __syncthreads();

    float a[NPB], b[NPB];
#pragma unroll
    for (int n = 0; n < NPB; n++) { a[n] = 0.f; b[n] = 0.f; }

#pragma unroll 8
    for (int k = 0; k < ZD; k++) {
        float ws = W1[k * HID + tid];
        float wd = W1[(ZD + k) * HID + tid];
#pragma unroll
        for (int n = 0; n < NPB; n++) {
            float zk = zs[n * ZD + k];
            a[n] = fmaf(zk, ws, a[n]);
            b[n] = fmaf(zk, wd, b[n]);
        }
    }
    for (int n = 0; n < nn; n++) {
        g_A[(base + n) * HID + tid] = a[n];
        g_B[(base + n) * HID + tid] = b[n];
    }
}

// ---------------- K1: BN statistics pass — warp-per-edge float4 gather ----------------
template<bool IS64>
__device__ __forceinline__ void k1_body(const void* __restrict__ ei, int E, int per) {
    int tid = threadIdx.x;
    int fq = tid & 31, eq = tid >> 5;
    int e0 = blockIdx.x * per;
    int e1 = e0 + per; if (e1 > E) e1 = E;

    const float4* A4 = (const float4*)g_A;   // row stride = 32 float4
    const float4* B4 = (const float4*)g_B;
    float4 dv = ((const float4*)g_d)[fq];
    float4 S1 = make_float4(0.f, 0.f, 0.f, 0.f);
    float4 S2 = make_float4(0.f, 0.f, 0.f, 0.f);

    const int*       p32 = (const int*)ei;
    const long long* p64 = (const long long*)ei;
    int n4 = (e1 > e0) ? ((e1 - e0) >> 2) : 0;

    for (int q = eq; q < n4; q += 4) {
        int ebase = e0 + q * 4;
        int s[4], t[4];
        if (IS64) {
            longlong2 sa = *(const longlong2*)(p64 + ebase);
            longlong2 sb = *(const longlong2*)(p64 + ebase + 2);
            longlong2 ta = *(const longlong2*)(p64 + (long long)E + ebase);
            longlong2 tb = *(const longlong2*)(p64 + (long long)E + ebase + 2);
            s[0] = (int)sa.x; s[1] = (int)sa.y; s[2] = (int)sb.x; s[3] = (int)sb.y;
            t[0] = (int)ta.x; t[1] = (int)ta.y; t[2] = (int)tb.x; t[3] = (int)tb.y;
        } else {
            int4 si = *(const int4*)(p32 + ebase);
            int4 ti = *(const int4*)(p32 + (long long)E + ebase);
            s[0] = si.x; s[1] = si.y; s[2] = si.z; s[3] = si.w;
            t[0] = ti.x; t[1] = ti.y; t[2] = ti.z; t[3] = ti.w;
        }
        float4 a[4], b[4];
#pragma unroll
        for (int j = 0; j < 4; j++) a[j] = A4[s[j] * 32 + fq];
#pragma unroll
        for (int j = 0; j < 4; j++) b[j] = B4[t[j] * 32 + fq];
#pragma unroll
        for (int j = 0; j < 4; j++) {
            float h0 = fmaxf(a[j].x + b[j].x + dv.x, 0.f);
            float h1 = fmaxf(a[j].y + b[j].y + dv.y, 0.f);
            float h2 = fmaxf(a[j].z + b[j].z + dv.z, 0.f);
            float h3 = fmaxf(a[j].w + b[j].w + dv.w, 0.f);
            S1.x += h0; S1.y += h1; S1.z += h2; S1.w += h3;
            S2.x = fmaf(h0, h0, S2.x); S2.y = fmaf(h1, h1, S2.y);
            S2.z = fmaf(h2, h2, S2.z); S2.w = fmaf(h3, h3, S2.w);
        }
    }
    // scalar tail (at most 3 edges)
    for (int e = e0 + n4 * 4 + eq; e < e1; e += 4) {
        int s = IS64 ? (int)p64[e] : p32[e];
        int t = IS64 ? (int)p64[(long long)E + e] : p32[(long long)E + e];
        float4 a = A4[s * 32 + fq], b = B4[t * 32 + fq];
        float h0 = fmaxf(a.x + b.x + dv.x, 0.f);
        float h1 = fmaxf(a.y + b.y + dv.y, 0.f);
        float h2 = fmaxf(a.z + b.z + dv.z, 0.f);
        float h3 = fmaxf(a.w + b.w + dv.w, 0.f);
        S1.x += h0; S1.y += h1; S1.z += h2; S1.w += h3;
        S2.x = fmaf(h0, h0, S2.x); S2.y = fmaf(h1, h1, S2.y);
        S2.z = fmaf(h2, h2, S2.z); S2.w = fmaf(h3, h3, S2.w);
    }

    // block reduction across the 4 eq-warps, then one atomic per feature
    __shared__ float sm1[4][HID], sm2[4][HID];
    sm1[eq][fq * 4 + 0] = S1.x; sm1[eq][fq * 4 + 1] = S1.y;
    sm1[eq][fq * 4 + 2] = S1.z; sm1[eq][fq * 4 + 3] = S1.w;
    sm2[eq][fq * 4 + 0] = S2.x; sm2[eq][fq * 4 + 1] = S2.y;
    sm2[eq][fq * 4 + 2] = S2.z; sm2[eq][fq * 4 + 3] = S2.w;
    __syncthreads();
    float v1 = sm1[0][tid] + sm1[1][tid] + sm1[2][tid] + sm1[3][tid];
    float v2 = sm2[0][tid] + sm2[1][tid] + sm2[2][tid] + sm2[3][tid];
    atomicAdd(&g_sum[tid],   (double)v1);
    atomicAdd(&g_sumsq[tid], (double)v2);
}

__global__ void __launch_bounds__(128, 8) k1_stats(const void* __restrict__ ei, int E, int per) {
    if (g_is64) k1_body<true>(ei, E, per);
    else        k1_body<false>(ei, E, per);
}

// ---------------- K1.5: fold BN into W2 -> fp16 hi/lo (PARALLEL: 128 blocks) ----------------
__global__ void k15_fold(const float* __restrict__ gamma, const float* __restrict__ beta,
                         const float* __restrict__ W2, const float* __restrict__ b2,
                         const float* __restrict__ W3, double invE) {
    __shared__ float red[4];
    int i = blockIdx.x;    // output feature f
    int k = threadIdx.x;   // input feature k
    int lane = k & 31, wrp = k >> 5;

    double m = g_sum[k] * invE;
    double v = g_sumsq[k] * invE - m * m;
    float x = (float)v + 1e-5f;
    float s = rsqrtf(x);
    s = s * (1.5f - 0.5f * x * s * s);  // Newton refine
    float g = s * gamma[k];
    float gsc_k = g;
    float gsh_k = beta[k] - (float)m * g;

    float w = W2[k * HID + i];           // W2[k][f=i]
    float wf = gsc_k * w;                // BN scale folded
    __half hb = __float2half(wf);
    float hf = __half2float(hb);
    __half lb = __float2half(wf - hf);
    int o = bofs(i, k) >> 1;             // row = feature f, col = k
    g_Whi[o] = *(const unsigned short*)&hb;
    g_Wlo[o] = *(const unsigned short*)&lb;

    float bb = gsh_k * w;
#pragma unroll
    for (int d = 16; d > 0; d >>= 1) bb += __shfl_xor_sync(0xffffffffu, bb, d);
    if (lane == 0) red[wrp] = bb;
    __syncthreads();
    if (k == 0) {
        float tot = red[0] + red[1] + red[2] + red[3];
        g_w3b2[i] = make_float2(b2[i] + tot, W3[i]);
    }
}

// ---------------- K2: warp-specialized producer/consumer, fp16 2-pass MMA ----------------
// 384 threads: warps 0-7 = MMA consumers (each m=64 x n=32),
// warps 8-11 = pipelined gather producers + output epilogue.
// h stored as SINGLE fp16 (error 2^-12 RMS); W2' split fp16 hi+lo -> 2 passes.
// smem (1024-aligned base):
#define OFF_WHI 0
#define OFF_WLO 32768
#define OFF_H(buf) (65536 + (buf) * 32768)
#define OFF_SWB 131072          // w3b2 float2[128] (1KB)
#define OFF_SRED 132096         // sred[4][128] floats (2KB)
#define K2_SMEM (134144 + 1024)

// producer: coalesced gather + relu + fp16 pack, SOFTWARE-PIPELINED.
static __device__ __forceinline__ void k2_produce(
    int tile, long long E, int is64, const long long* p64, const int* p32,
    const float4* dq, char* aH, int lg, int gr)
{
    int sa[8], ta[8];
#pragma unroll
    for (int p = 0; p < 8; p++) {
        long long ge = (long long)tile * TM + p * 16 + gr;
        long long g2 = (ge < E) ? ge : (long long)0;
        sa[p] = is64 ? (int)p64[g2] : p32[g2];
        ta[p] = is64 ? (int)p64[E + g2] : p32[E + g2];
    }

    float4 av[2][4], bv[2][4];
    {
        const float4* ap = (const float4*)(g_A + (size_t)sa[0] * HID) + lg;
        const float4* bp = (const float4*)(g_B + (size_t)ta[0] * HID) + lg;
#pragma unroll
        for (int i = 0; i < 4; i++) av[0][i] = ap[i * 8];
#pragma unroll
        for (int i = 0; i < 4; i++) bv[0][i] = bp[i * 8];
    }

#pragma unroll
    for (int p = 0; p < 8; p++) {
        int cur = p & 1;
        if (p < 7) {
            const float4* ap = (const float4*)(g_A + (size_t)sa[p + 1] * HID) + lg;
            const float4* bp = (const float4*)(g_B + (size_t)ta[p + 1] * HID) + lg;
#pragma unroll
            for (int i = 0; i < 4; i++) av[cur ^ 1][i] = ap[i * 8];
#pragma unroll
            for (int i = 0; i < 4; i++) bv[cur ^ 1][i] = bp[i * 8];
        }
        int r = p * 16 + gr;
#pragma unroll
        for (int i = 0; i < 4; i++) {
            float4 d = dq[i];
            float4 a = av[cur][i], b = bv[cur][i];
            float h0 = fmaxf(a.x + b.x + d.x, 0.f);
            float h1 = fmaxf(a.y + b.y + d.y, 0.f);
            float h2 = fmaxf(a.z + b.z + d.z, 0.f);
            float h3 = fmaxf(a.w + b.w + d.w, 0.f);
            u32 ph0 = hf2(h0, h1), ph1 = hf2(h2, h3);
            int o = bofs(r, i * 32 + lg * 4);
            *(uint2*)(aH + o) = make_uint2(ph0, ph1);
        }
    }
}

__global__ void __launch_bounds__(384, 1)
k2_main(const void* __restrict__ ei, const float* __restrict__ b3,
        float* __restrict__ out, int E, int ntiles) {
    extern __shared__ char dsm[];
    u32 braw = smem_u32(dsm);
    u32 base = (braw + 1023u) & ~1023u;
    char* sm = dsm + (base - braw);

    int tid  = threadIdx.x;
    int wid  = tid >> 5, lane = tid & 31;
    int is64 = g_is64;
    const long long* p64 = (const long long*)ei;
    const int*       p32 = (const int*)ei;

    const float2* swb = (const float2*)(sm + OFF_SWB);
    float* sred = (float*)(sm + OFF_SRED);

    // stage W2' fp16 hi/lo + w3b2 into smem (all 384 threads)
    {
        uint4* dh = (uint4*)(sm + OFF_WHI);
        uint4* dl = (uint4*)(sm + OFF_WLO);
        const uint4* shi = (const uint4*)g_Whi;
        const uint4* slo = (const uint4*)g_Wlo;
        for (int i = tid; i < 2048; i += 384) { dh[i] = shi[i]; dl[i] = slo[i]; }
        if (tid < HID) ((float2*)(sm + OFF_SWB))[tid] = g_w3b2[tid];
    }
    float bias3 = b3[0];
    u32 wHiB = base + OFF_WHI, wLoB = base + OFF_WLO;

    // consumer constants: warp tile = m 64 (wm 0..1) x n 32 (wn 0..3)
    int wm = (wid >> 2) & 1, wn = wid & 3;
    int li = lane & 7, grp = lane >> 3;
    int kgA = (grp >> 1) * 8;
    int kgB = (grp & 1) * 8;
    int nB0 = 32 * wn + (grp >> 1) * 8 + li;
    int nB1 = nB0 + 16;
    int bq0 = ((nB0 >> 3) << 10) + ((nB0 & 7) << 7);
    int bq1 = ((nB1 >> 3) << 10) + ((nB1 & 7) << 7);
    // A row-part per mt (4 x m16 tiles)
    int rp[4];
#pragma unroll
    for (int mt = 0; mt < 4; mt++) {
        int rA = wm * 64 + mt * 16 + (grp & 1) * 8 + li;
        rp[mt] = ((rA >> 3) << 10) + ((rA & 7) << 7);
    }

    // producer constants
    int tid_p = tid - 256;
    int lg = tid_p & 7, gr = tid_p >> 3;
    float4 dq[4];
    if (wid >= 8) {
#pragma unroll
        for (int i = 0; i < 4; i++) dq[i] = ((const float4*)g_d)[i * 8 + lg];
    }

    __syncthreads();  // W, swb staged

    // prologue: producers fill buf0 with this block's first tile
    int first = blockIdx.x;
    if (wid >= 8 && first < ntiles)
        k2_produce(first, E, is64, p64, p32, dq, sm + OFF_H(0), lg, gr);

    int iter = 0;
    for (int tile = first; tile < ntiles; tile += gridDim.x, iter++) {
        int buf = iter & 1;
        __syncthreads();  // H[buf] ready; H[buf^1] free; sred(prev) consumed by producers

        if (wid < 8) {
            // ============ CONSUMERS: fp16 2-pass MMA, m64 x n32 per warp ============
            u32 hB = base + OFF_H(buf);

            float acc[4][4][4];
#pragma unroll
            for (int mt = 0; mt < 4; mt++)
#pragma unroll
                for (int nt = 0; nt < 4; nt++)
#pragma unroll
                    for (int q = 0; q < 4; q++) acc[mt][nt][q] = 0.f;

#pragma unroll 1
            for (int ks = 0; ks < 8; ks++) {
                int k0 = ks * 16;
                int kkA = k0 + kgA;
                int kpA = ((kkA >> 6) << 14) + ((kkA & 63) << 1);
                int kkB = k0 + kgB;
                int kpB = ((kkB >> 6) << 14) + ((kkB & 63) << 1);
                int oB0 = bq0 + kpB; oB0 ^= ((oB0 >> 3) & 0x70);
                int oB1 = bq1 + kpB; oB1 ^= ((oB1 >> 3) & 0x70);

                u32 bh0[4], bh1[4], bl0[4], bl1[4];
                ldsm4(bh0, wHiB + (u32)oB0);
                ldsm4(bh1, wHiB + (u32)oB1);
                ldsm4(bl0, wLoB + (u32)oB0);
                ldsm4(bl1, wLoB + (u32)oB1);

                u32 aF[4][4];
#pragma unroll
                for (int mt = 0; mt < 4; mt++) {
                    int oA = rp[mt] + kpA; oA ^= ((oA >> 3) & 0x70);
                    ldsm4(aF[mt], hB + (u32)oA);
                }

                // pass 1: h x W-hi
#pragma unroll
                for (int mt = 0; mt < 4; mt++) {
                    mma16816(acc[mt][0], aF[mt], bh0[0], bh0[1]);
                    mma16816(acc[mt][1], aF[mt], bh0[2], bh0[3]);
                    mma16816(acc[mt][2], aF[mt], bh1[0], bh1[1]);
                    mma16816(acc[mt][3], aF[mt], bh1[2], bh1[3]);
                }
                // pass 2: h x W-lo
#pragma unroll
                for (int mt = 0; mt < 4; mt++) {
                    mma16816(acc[mt][0], aF[mt], bl0[0], bl0[1]);
                    mma16816(acc[mt][1], aF[mt], bl0[2], bl0[3]);
                    mma16816(acc[mt][2], aF[mt], bl1[0], bl1[1]);
                    mma16816(acc[mt][3], aF[mt], bl1[2], bl1[3]);
                }
            }

            // epilogue (consumer part): relu(acc + b2') . w3, quad-reduce, stash partials
#pragma unroll
            for (int mt = 0; mt < 4; mt++) {
                float pl = 0.f, ph = 0.f;
#pragma unroll
                for (int nt = 0; nt < 4; nt++)
#pragma unroll
                    for (int cp = 0; cp < 2; cp++) {
                        float2 w = swb[32 * wn + nt * 8 + 2 * (lane & 3) + cp];
                        pl = fmaf(fmaxf(acc[mt][nt][cp]     + w.x, 0.f), w.y, pl);
                        ph = fmaf(fmaxf(acc[mt][nt][2 + cp] + w.x, 0.f), w.y, ph);
                    }
                pl += __shfl_xor_sync(0xffffffffu, pl, 1);
                pl += __shfl_xor_sync(0xffffffffu, pl, 2);
                ph += __shfl_xor_sync(0xffffffffu, ph, 1);
                ph += __shfl_xor_sync(0xffffffffu, ph, 2);
                if ((lane & 3) == 0) {
                    int r = wm * 64 + mt * 16 + (lane >> 2);
                    sred[wn * 128 + r]     = pl;
                    sred[wn * 128 + r + 8] = ph;
                }
            }
            // non-blocking arrive: producers pick up the final sum + store
            asm volatile("bar.arrive 1, 384;" ::: "memory");
        } else {
            // ============ PRODUCERS: transform tile+grid into H[buf^1], then output epilogue ============
            int nt = tile + gridDim.x;
            if (nt < ntiles)
                k2_produce(nt, E, is64, p64, p32, dq, sm + OFF_H(buf ^ 1), lg, gr);

            asm volatile("bar.sync 1, 384;" ::: "memory");  // wait for consumer sred
            long long ge = (long long)tile * TM + tid_p;
            if (ge < E) {
                float v = sred[tid_p] + sred[128 + tid_p] + sred[256 + tid_p] + sred[384 + tid_p];
                out[ge] = v + bias3;
            }
        }
    }
}

// ---------------- launch ----------------
extern "C" void kernel_launch(void* const* d_in, const int* in_sizes, int n_in,
                              void* d_out, int out_size) {
    const float* z     = (const float*)d_in[0];
    const void*  ei    = d_in[1];
    const float* c     = (const float*)d_in[2];
    const float* W1    = (const float*)d_in[3];
    const float* b1    = (const float*)d_in[4];
    const float* gamma = (const float*)d_in[5];
    const float* beta  = (const float*)d_in[6];
    const float* W2    = (const float*)d_in[7];
    const float* b2    = (const float*)d_in[8];
    const float* W3    = (const float*)d_in[9];
    const float* b3    = (const float*)d_in[10];
    float* out = (float*)d_out;

    int N = in_sizes[0] / ZD;
    int E = in_sizes[1] / 2;

    cudaFuncSetAttribute(k2_main, cudaFuncAttributeMaxDynamicSharedMemorySize, K2_SMEM);

    k0_nodes<<<(N + NPB - 1) / NPB + 1, 128>>>(z, W1, N, (const unsigned int*)ei, c, b1);
    int per = (((E + K1_BLOCKS - 1) / K1_BLOCKS) + 3) & ~3;   // 4-aligned per-block edge range
    k1_stats<<<K1_BLOCKS, 128>>>(ei, E, per);
    k15_fold<<<HID, 128>>>(gamma, beta, W2, b2, W3, 1.0 / (double)E);
    int ntiles = (E + TM - 1) / TM;
    k2_main<<<K2_GRID, 384, K2_SMEM>>>(ei, b3, out, E, ntiles);
}

// round 17
// speedup vs baseline: 1.5414x; 1.0827x over previous
#include <cuda_runtime.h>
#include <cuda_bf16.h>
#include <cuda_fp16.h>
#include <stdint.h>

#define NODES_MAX 50000
#define HID 128
#define ZD 64
#define NPB 16          // nodes per block in K0
#define TM 128          // edges per tile in K2
#define K1_BLOCKS 1184  // 148 SMs * 8
#define K2_GRID 148

typedef unsigned long long u64;
typedef unsigned int u32;

// ---------------- static device scratch ----------------
__device__ float  g_A[NODES_MAX * HID];     // z @ W1[0:64]
__device__ float  g_B[NODES_MAX * HID];     // z @ W1[64:128]
__device__ float  g_d[HID];                 // c @ W1[128:132] + b1
__device__ double g_sum[HID];
__device__ double g_sumsq[HID];
__device__ unsigned short g_Whi[16384];     // BN-folded W2 fp16, MMA swizzled layout
__device__ float2 g_w3b2[HID];              // (b2_folded, w3) per feature
__device__ int    g_is64;

// ---------------- helpers ----------------
__device__ __forceinline__ u32 smem_u32(const void* p) {
    u32 a;
    asm("{ .reg .u64 t; cvta.to.shared.u64 t, %1; cvt.u32.u64 %0, t; }" : "=r"(a) : "l"(p));
    return a;
}
// packed fp16x2 convert: low half <- lo, high half <- hi
__device__ __forceinline__ u32 hf2(float lo, float hi) {
    u32 r;
    asm("cvt.rn.f16x2.f32 %0, %1, %2;" : "=r"(r) : "f"(hi), "f"(lo));
    return r;
}
__device__ __forceinline__ void ldsm4(u32* r, u32 addr) {
    asm volatile("ldmatrix.sync.aligned.m8n8.x4.shared.b16 {%0,%1,%2,%3}, [%4];"
                 : "=r"(r[0]), "=r"(r[1]), "=r"(r[2]), "=r"(r[3]) : "r"(addr));
}
__device__ __forceinline__ void mma16816(float* c, const u32* a, u32 b0, u32 b1) {
    asm volatile(
        "mma.sync.aligned.m16n8k16.row.col.f32.f16.f16.f32 "
        "{%0,%1,%2,%3}, {%4,%5,%6,%7}, {%8,%9}, {%0,%1,%2,%3};"
        : "+f"(c[0]), "+f"(c[1]), "+f"(c[2]), "+f"(c[3])
        : "r"(a[0]), "r"(a[1]), "r"(a[2]), "r"(a[3]), "r"(b0), "r"(b1));
}

// MMA-layout byte offset for element (row r, col k) in a 128x128 fp16 K-major
// SW128 blocked-atom tile: atom = 8 rows x 64 fp16 (1024B), 16 atom-rows x 2 atom-cols.
__device__ __forceinline__ int bofs(int r, int k) {
    int off = ((r >> 3) << 10) + ((k >> 6) << 14) + ((r & 7) << 7) + ((k & 63) << 1);
    return off ^ ((off >> 3) & 0x70);
}

// ---------------- K0: per-node partial products (+fused detect & k0b in extra block) ----------------
__global__ void k0_nodes(const float* __restrict__ z, const float* __restrict__ W1, int N,
                         const unsigned int* __restrict__ eiw,
                         const float* __restrict__ c, const float* __restrict__ b1) {
    __shared__ float zs[NPB * ZD];
    int tid = threadIdx.x;

    if (blockIdx.x == gridDim.x - 1) {
        // --- fused k_detect: is edge_index int64 or int32? ---
        __shared__ int nz;
        if (tid == 0) nz = 0;
        __syncthreads();
        if (eiw[2 * tid + 1] != 0u) atomicAdd(&nz, 1);
        __syncthreads();
        if (tid == 0) g_is64 = (nz == 0) ? 1 : 0;
        // --- fused k0b: d = c@W1c + b1, zero BN accumulators ---
        float v = b1[tid];
#pragma unroll
        for (int k = 0; k < 4; k++) v = fmaf(c[k], W1[(2 * ZD + k) * HID + tid], v);
        g_d[tid]     = v;
        g_sum[tid]   = 0.0;
        g_sumsq[tid] = 0.0;
        return;
    }

    int base = blockIdx.x * NPB;
    int nn   = N - base; if (nn > NPB) nn = NPB;

    for (int i = tid; i < nn * ZD; i += 128) zs[i] = z[base * ZD + i];
    __syncthreads();

    float a[NPB], b[NPB];
#pragma unroll
    for (int n = 0; n < NPB; n++) { a[n] = 0.f; b[n] = 0.f; }

#pragma unroll 8
    for (int k = 0; k < ZD; k++) {
        float ws = W1[k * HID + tid];
        float wd = W1[(ZD + k) * HID + tid];
#pragma unroll
        for (int n = 0; n < NPB; n++) {
            float zk = zs[n * ZD + k];
            a[n] = fmaf(zk, ws, a[n]);
            b[n] = fmaf(zk, wd, b[n]);
        }
    }
    for (int n = 0; n < nn; n++) {
        g_A[(base + n) * HID + tid] = a[n];
        g_B[(base + n) * HID + tid] = b[n];
    }
}

// ---------------- K1: BN statistics pass — warp-per-edge float4 gather ----------------
template<bool IS64>
__device__ __forceinline__ void k1_body(const void* __restrict__ ei, int E, int per) {
    int tid = threadIdx.x;
    int fq = tid & 31, eq = tid >> 5;
    int e0 = blockIdx.x * per;
    int e1 = e0 + per; if (e1 > E) e1 = E;

    const float4* A4 = (const float4*)g_A;   // row stride = 32 float4
    const float4* B4 = (const float4*)g_B;
    float4 dv = ((const float4*)g_d)[fq];
    float4 S1 = make_float4(0.f, 0.f, 0.f, 0.f);
    float4 S2 = make_float4(0.f, 0.f, 0.f, 0.f);

    const int*       p32 = (const int*)ei;
    const long long* p64 = (const long long*)ei;
    int n4 = (e1 > e0) ? ((e1 - e0) >> 2) : 0;

    for (int q = eq; q < n4; q += 4) {
        int ebase = e0 + q * 4;
        int s[4], t[4];
        if (IS64) {
            longlong2 sa = *(const longlong2*)(p64 + ebase);
            longlong2 sb = *(const longlong2*)(p64 + ebase + 2);
            longlong2 ta = *(const longlong2*)(p64 + (long long)E + ebase);
            longlong2 tb = *(const longlong2*)(p64 + (long long)E + ebase + 2);
            s[0] = (int)sa.x; s[1] = (int)sa.y; s[2] = (int)sb.x; s[3] = (int)sb.y;
            t[0] = (int)ta.x; t[1] = (int)ta.y; t[2] = (int)tb.x; t[3] = (int)tb.y;
        } else {
            int4 si = *(const int4*)(p32 + ebase);
            int4 ti = *(const int4*)(p32 + (long long)E + ebase);
            s[0] = si.x; s[1] = si.y; s[2] = si.z; s[3] = si.w;
            t[0] = ti.x; t[1] = ti.y; t[2] = ti.z; t[3] = ti.w;
        }
        float4 a[4], b[4];
#pragma unroll
        for (int j = 0; j < 4; j++) a[j] = A4[s[j] * 32 + fq];
#pragma unroll
        for (int j = 0; j < 4; j++) b[j] = B4[t[j] * 32 + fq];
#pragma unroll
        for (int j = 0; j < 4; j++) {
            float h0 = fmaxf(a[j].x + b[j].x + dv.x, 0.f);
            float h1 = fmaxf(a[j].y + b[j].y + dv.y, 0.f);
            float h2 = fmaxf(a[j].z + b[j].z + dv.z, 0.f);
            float h3 = fmaxf(a[j].w + b[j].w + dv.w, 0.f);
            S1.x += h0; S1.y += h1; S1.z += h2; S1.w += h3;
            S2.x = fmaf(h0, h0, S2.x); S2.y = fmaf(h1, h1, S2.y);
            S2.z = fmaf(h2, h2, S2.z); S2.w = fmaf(h3, h3, S2.w);
        }
    }
    // scalar tail (at most 3 edges)
    for (int e = e0 + n4 * 4 + eq; e < e1; e += 4) {
        int s = IS64 ? (int)p64[e] : p32[e];
        int t = IS64 ? (int)p64[(long long)E + e] : p32[(long long)E + e];
        float4 a = A4[s * 32 + fq], b = B4[t * 32 + fq];
        float h0 = fmaxf(a.x + b.x + dv.x, 0.f);
        float h1 = fmaxf(a.y + b.y + dv.y, 0.f);
        float h2 = fmaxf(a.z + b.z + dv.z, 0.f);
        float h3 = fmaxf(a.w + b.w + dv.w, 0.f);
        S1.x += h0; S1.y += h1; S1.z += h2; S1.w += h3;
        S2.x = fmaf(h0, h0, S2.x); S2.y = fmaf(h1, h1, S2.y);
        S2.z = fmaf(h2, h2, S2.z); S2.w = fmaf(h3, h3, S2.w);
    }

    // block reduction across the 4 eq-warps, then one atomic per feature
    __shared__ float sm1[4][HID], sm2[4][HID];
    sm1[eq][fq * 4 + 0] = S1.x; sm1[eq][fq * 4 + 1] = S1.y;
    sm1[eq][fq * 4 + 2] = S1.z; sm1[eq][fq * 4 + 3] = S1.w;
    sm2[eq][fq * 4 + 0] = S2.x; sm2[eq][fq * 4 + 1] = S2.y;
    sm2[eq][fq * 4 + 2] = S2.z; sm2[eq][fq * 4 + 3] = S2.w;
    __syncthreads();
    float v1 = sm1[0][tid] + sm1[1][tid] + sm1[2][tid] + sm1[3][tid];
    float v2 = sm2[0][tid] + sm2[1][tid] + sm2[2][tid] + sm2[3][tid];
    atomicAdd(&g_sum[tid],   (double)v1);
    atomicAdd(&g_sumsq[tid], (double)v2);
}

__global__ void __launch_bounds__(128, 8) k1_stats(const void* __restrict__ ei, int E, int per) {
    if (g_is64) k1_body<true>(ei, E, per);
    else        k1_body<false>(ei, E, per);
}

// ---------------- K1.5: fold BN into W2 -> single fp16 (PARALLEL: 128 blocks) ----------------
__global__ void k15_fold(const float* __restrict__ gamma, const float* __restrict__ beta,
                         const float* __restrict__ W2, const float* __restrict__ b2,
                         const float* __restrict__ W3, double invE) {
    __shared__ float red[4];
    int i = blockIdx.x;    // output feature f
    int k = threadIdx.x;   // input feature k
    int lane = k & 31, wrp = k >> 5;

    double m = g_sum[k] * invE;
    double v = g_sumsq[k] * invE - m * m;
    float x = (float)v + 1e-5f;
    float s = rsqrtf(x);
    s = s * (1.5f - 0.5f * x * s * s);  // Newton refine
    float g = s * gamma[k];
    float gsc_k = g;
    float gsh_k = beta[k] - (float)m * g;

    float w = W2[k * HID + i];           // W2[k][f=i]
    float wf = gsc_k * w;                // BN scale folded
    __half hb = __float2half(wf);
    int o = bofs(i, k) >> 1;             // row = feature f, col = k
    g_Whi[o] = *(const unsigned short*)&hb;

    float bb = gsh_k * w;
#pragma unroll
    for (int d = 16; d > 0; d >>= 1) bb += __shfl_xor_sync(0xffffffffu, bb, d);
    if (lane == 0) red[wrp] = bb;
    __syncthreads();
    if (k == 0) {
        float tot = red[0] + red[1] + red[2] + red[3];
        g_w3b2[i] = make_float2(b2[i] + tot, W3[i]);
    }
}

// ---------------- K2: warp-specialized producer/consumer, fp16 1-pass MMA ----------------
// 640 threads: warps 0-15 = MMA consumers (each m=32 x n=32, 4 warps/SMSP for
// ldsm-latency interleave), warps 16-19 = pipelined gather producers + output epilogue.
// smem (1024-aligned base):
#define OFF_WHI 0
#define OFF_H(buf) (32768 + (buf) * 32768)
#define OFF_SWB 98304           // w3b2 float2[128] (1KB)
#define OFF_SRED 99328          // sred[4][128] floats (2KB)
#define K2_SMEM (101376 + 1024)

// producer: coalesced gather + relu + fp16 pack, SOFTWARE-PIPELINED.
static __device__ __forceinline__ void k2_produce(
    int tile, long long E, int is64, const long long* p64, const int* p32,
    const float4* dq, char* aH, int lg, int gr)
{
    int sa[8], ta[8];
#pragma unroll
    for (int p = 0; p < 8; p++) {
        long long ge = (long long)tile * TM + p * 16 + gr;
        long long g2 = (ge < E) ? ge : (long long)0;
        sa[p] = is64 ? (int)p64[g2] : p32[g2];
        ta[p] = is64 ? (int)p64[E + g2] : p32[E + g2];
    }

    float4 av[2][4], bv[2][4];
    {
        const float4* ap = (const float4*)(g_A + (size_t)sa[0] * HID) + lg;
        const float4* bp = (const float4*)(g_B + (size_t)ta[0] * HID) + lg;
#pragma unroll
        for (int i = 0; i < 4; i++) av[0][i] = ap[i * 8];
#pragma unroll
        for (int i = 0; i < 4; i++) bv[0][i] = bp[i * 8];
    }

#pragma unroll
    for (int p = 0; p < 8; p++) {
        int cur = p & 1;
        if (p < 7) {
            const float4* ap = (const float4*)(g_A + (size_t)sa[p + 1] * HID) + lg;
            const float4* bp = (const float4*)(g_B + (size_t)ta[p + 1] * HID) + lg;
#pragma unroll
            for (int i = 0; i < 4; i++) av[cur ^ 1][i] = ap[i * 8];
#pragma unroll
            for (int i = 0; i < 4; i++) bv[cur ^ 1][i] = bp[i * 8];
        }
        int r = p * 16 + gr;
#pragma unroll
        for (int i = 0; i < 4; i++) {
            float4 d = dq[i];
            float4 a = av[cur][i], b = bv[cur][i];
            float h0 = fmaxf(a.x + b.x + d.x, 0.f);
            float h1 = fmaxf(a.y + b.y + d.y, 0.f);
            float h2 = fmaxf(a.z + b.z + d.z, 0.f);
            float h3 = fmaxf(a.w + b.w + d.w, 0.f);
            u32 ph0 = hf2(h0, h1), ph1 = hf2(h2, h3);
            int o = bofs(r, i * 32 + lg * 4);
            *(uint2*)(aH + o) = make_uint2(ph0, ph1);
        }
    }
}

__global__ void __launch_bounds__(640, 1)
k2_main(const void* __restrict__ ei, const float* __restrict__ b3,
        float* __restrict__ out, int E, int ntiles) {
    extern __shared__ char dsm[];
    u32 braw = smem_u32(dsm);
    u32 base = (braw + 1023u) & ~1023u;
    char* sm = dsm + (base - braw);

    int tid  = threadIdx.x;
    int wid  = tid >> 5, lane = tid & 31;
    int is64 = g_is64;
    const long long* p64 = (const long long*)ei;
    const int*       p32 = (const int*)ei;

    const float2* swb = (const float2*)(sm + OFF_SWB);
    float* sred = (float*)(sm + OFF_SRED);

    // stage W2' fp16 + w3b2 into smem (all 640 threads)
    {
        uint4* dh = (uint4*)(sm + OFF_WHI);
        const uint4* shi = (const uint4*)g_Whi;
        for (int i = tid; i < 2048; i += 640) dh[i] = shi[i];
        if (tid < HID) ((float2*)(sm + OFF_SWB))[tid] = g_w3b2[tid];
    }
    float bias3 = b3[0];
    u32 wHiB = base + OFF_WHI;

    // consumer constants: warp tile = m 32 (wm 0..3) x n 32 (wn 0..3)
    int wm = (wid >> 2) & 3, wn = wid & 3;
    int li = lane & 7, grp = lane >> 3;
    int kgA = (grp >> 1) * 8;
    int kgB = (grp & 1) * 8;
    int nB0 = 32 * wn + (grp >> 1) * 8 + li;
    int nB1 = nB0 + 16;
    int bq0 = ((nB0 >> 3) << 10) + ((nB0 & 7) << 7);
    int bq1 = ((nB1 >> 3) << 10) + ((nB1 & 7) << 7);
    // A row-part per mt (2 x m16 tiles)
    int rp[2];
#pragma unroll
    for (int mt = 0; mt < 2; mt++) {
        int rA = wm * 32 + mt * 16 + (grp & 1) * 8 + li;
        rp[mt] = ((rA >> 3) << 10) + ((rA & 7) << 7);
    }

    // producer constants
    int tid_p = tid - 512;
    int lg = tid_p & 7, gr = tid_p >> 3;
    float4 dq[4];
    if (wid >= 16) {
#pragma unroll
        for (int i = 0; i < 4; i++) dq[i] = ((const float4*)g_d)[i * 8 + lg];
    }

    __syncthreads();  // W, swb staged

    // prologue: producers fill buf0 with this block's first tile
    int first = blockIdx.x;
    if (wid >= 16 && first < ntiles)
        k2_produce(first, E, is64, p64, p32, dq, sm + OFF_H(0), lg, gr);

    int iter = 0;
    for (int tile = first; tile < ntiles; tile += gridDim.x, iter++) {
        int buf = iter & 1;
        __syncthreads();  // H[buf] ready; H[buf^1] free; sred(prev) consumed by producers

        if (wid < 16) {
            // ============ CONSUMERS: fp16 1-pass MMA, m32 x n32 per warp ============
            u32 hB = base + OFF_H(buf);

            float acc[2][4][4];
#pragma unroll
            for (int mt = 0; mt < 2; mt++)
#pragma unroll
                for (int nt = 0; nt < 4; nt++)
#pragma unroll
                    for (int q = 0; q < 4; q++) acc[mt][nt][q] = 0.f;

#pragma unroll 1
            for (int ks = 0; ks < 8; ks++) {
                int k0 = ks * 16;
                int kkA = k0 + kgA;
                int kpA = ((kkA >> 6) << 14) + ((kkA & 63) << 1);
                int kkB = k0 + kgB;
                int kpB = ((kkB >> 6) << 14) + ((kkB & 63) << 1);
                int oB0 = bq0 + kpB; oB0 ^= ((oB0 >> 3) & 0x70);
                int oB1 = bq1 + kpB; oB1 ^= ((oB1 >> 3) & 0x70);

                u32 bh0[4], bh1[4];
                ldsm4(bh0, wHiB + (u32)oB0);
                ldsm4(bh1, wHiB + (u32)oB1);

#pragma unroll
                for (int mt = 0; mt < 2; mt++) {
                    int oA = rp[mt] + kpA; oA ^= ((oA >> 3) & 0x70);
                    u32 aF[4];
                    ldsm4(aF, hB + (u32)oA);
                    mma16816(acc[mt][0], aF, bh0[0], bh0[1]);
                    mma16816(acc[mt][1], aF, bh0[2], bh0[3]);
                    mma16816(acc[mt][2], aF, bh1[0], bh1[1]);
                    mma16816(acc[mt][3], aF, bh1[2], bh1[3]);
                }
            }

            // epilogue (consumer part): relu(acc + b2') . w3, quad-reduce, stash partials
#pragma unroll
            for (int mt = 0; mt < 2; mt++) {
                float pl = 0.f, ph = 0.f;
#pragma unroll
                for (int nt = 0; nt < 4; nt++)
#pragma unroll
                    for (int cp = 0; cp < 2; cp++) {
                        float2 w = swb[32 * wn + nt * 8 + 2 * (lane & 3) + cp];
                        pl = fmaf(fmaxf(acc[mt][nt][cp]     + w.x, 0.f), w.y, pl);
                        ph = fmaf(fmaxf(acc[mt][nt][2 + cp] + w.x, 0.f), w.y, ph);
                    }
                pl += __shfl_xor_sync(0xffffffffu, pl, 1);
                pl += __shfl_xor_sync(0xffffffffu, pl, 2);
                ph += __shfl_xor_sync(0xffffffffu, ph, 1);
                ph += __shfl_xor_sync(0xffffffffu, ph, 2);
                if ((lane & 3) == 0) {
                    int r = wm * 32 + mt * 16 + (lane >> 2);
                    sred[wn * 128 + r]     = pl;
                    sred[wn * 128 + r + 8] = ph;
                }
            }
            // non-blocking arrive: producers pick up the final sum + store
            asm volatile("bar.arrive 1, 640;" ::: "memory");
        } else {
            // ============ PRODUCERS: transform tile+grid into H[buf^1], then output epilogue ============
            int nt = tile + gridDim.x;
            if (nt < ntiles)
                k2_produce(nt, E, is64, p64, p32, dq, sm + OFF_H(buf ^ 1), lg, gr);

            asm volatile("bar.sync 1, 640;" ::: "memory");  // wait for consumer sred
            long long ge = (long long)tile * TM + tid_p;
            if (ge < E) {
                float v = sred[tid_p] + sred[128 + tid_p] + sred[256 + tid_p] + sred[384 + tid_p];
                out[ge] = v + bias3;
            }
        }
    }
}

// ---------------- launch ----------------
extern "C" void kernel_launch(void* const* d_in, const int* in_sizes, int n_in,
                              void* d_out, int out_size) {
    const float* z     = (const float*)d_in[0];
    const void*  ei    = d_in[1];
    const float* c     = (const float*)d_in[2];
    const float* W1    = (const float*)d_in[3];
    const float* b1    = (const float*)d_in[4];
    const float* gamma = (const float*)d_in[5];
    const float* beta  = (const float*)d_in[6];
    const float* W2    = (const float*)d_in[7];
    const float* b2    = (const float*)d_in[8];
    const float* W3    = (const float*)d_in[9];
    const float* b3    = (const float*)d_in[10];
    float* out = (float*)d_out;

    int N = in_sizes[0] / ZD;
    int E = in_sizes[1] / 2;

    cudaFuncSetAttribute(k2_main, cudaFuncAttributeMaxDynamicSharedMemorySize, K2_SMEM);

    k0_nodes<<<(N + NPB - 1) / NPB + 1, 128>>>(z, W1, N, (const unsigned int*)ei, c, b1);
    int per = (((E + K1_BLOCKS - 1) / K1_BLOCKS) + 3) & ~3;   // 4-aligned per-block edge range
    k1_stats<<<K1_BLOCKS, 128>>>(ei, E, per);
    k15_fold<<<HID, 128>>>(gamma, beta, W2, b2, W3, 1.0 / (double)E);
    int ntiles = (E + TM - 1) / TM;
    k2_main<<<K2_GRID, 640, K2_SMEM>>>(ei, b3, out, E, ntiles);
}